// round 1
// baseline (speedup 1.0000x reference)
#include <cuda_runtime.h>
#include <math.h>

// AFMADEBlock: incremental triangular evaluation of the MADE autoregressive
// inverse. Coordinate j of the fixed point depends only on coords < j (masked
// weights are exact 0.0f), so the reference's 32 full network passes collapse
// into ONE pass that finalizes one degree-group per step.

#define Dd 32
#define Hh 256
#define Bb 4096
#define EPSf 1e-12f
#define RPW 2                 // rows per warp
#define NWARP 4               // warps per block
#define THREADS (NWARP * 32)

// Permuted+masked weights (hidden units sorted by degree). ~656KB, static.
__device__ __align__(16) float g_W0p[2][32][256];
__device__ __align__(16) float g_W1p[2][256][256];
__device__ __align__(16) float g_W2p[2][256][32];
__device__ __align__(16) float g_b0p[2][256];
__device__ __align__(16) float g_b1p[2][256];
__device__ __align__(16) float g_b2[2][32];

// deg(i) = (i % 31) + 1 for original hidden index i.
// Sorted order: degrees 1..8 have 9 units, degrees 9..31 have 8 units.
__device__ __forceinline__ int degS(int k) {
    return (k < 72) ? (k / 9 + 1) : ((k - 72) / 8 + 9);
}
__device__ __forceinline__ int permS(int k) {
    int d, jj;
    if (k < 72) { d = k / 9 + 1;        jj = k % 9; }
    else        { d = (k - 72) / 8 + 9; jj = (k - 72) % 8; }
    return (d - 1) + 31 * jj;   // original index of k-th sorted unit
}

__global__ void prep_kernel(
    const float* __restrict__ mu_W0, const float* __restrict__ mu_b0,
    const float* __restrict__ mu_W1, const float* __restrict__ mu_b1,
    const float* __restrict__ mu_W2, const float* __restrict__ mu_b2,
    const float* __restrict__ lv_W0, const float* __restrict__ lv_b0,
    const float* __restrict__ lv_W1, const float* __restrict__ lv_b1,
    const float* __restrict__ lv_W2, const float* __restrict__ lv_b2)
{
    int idx = blockIdx.x * blockDim.x + threadIdx.x;
    if (idx >= 2 * 256 * 256) return;
    int net = idx >> 16;
    int k   = (idx >> 8) & 255;   // sorted hidden row
    int c   = idx & 255;          // sorted hidden col

    const float* W0 = net ? lv_W0 : mu_W0;
    const float* b0 = net ? lv_b0 : mu_b0;
    const float* W1 = net ? lv_W1 : mu_W1;
    const float* b1 = net ? lv_b1 : mu_b1;
    const float* W2 = net ? lv_W2 : mu_W2;
    const float* b2 = net ? lv_b2 : mu_b2;

    int dk = degS(k), pk = permS(k);
    int dc = degS(c), pc = permS(c);

    // hidden->hidden: unit c receives from unit k iff deg(c) >= deg(k)
    g_W1p[net][k][c] = (dc >= dk) ? W1[pk * 256 + pc] : 0.f;
    // input->hidden: input row k (deg k+1) feeds unit c iff deg(c) >= k+1
    if (k < 32) g_W0p[net][k][c] = (dc >= (k + 1)) ? W0[k * 256 + pc] : 0.f;
    // hidden->output: output c (deg c+1) receives unit k iff c+1 > deg(k)
    if (c < 32) g_W2p[net][k][c] = ((c + 1) > dk) ? W2[pk * 32 + c] : 0.f;
    if (k == 0) {
        g_b0p[net][c] = b0[pc];
        g_b1p[net][c] = b1[pc];
        if (c < 32) g_b2[net][c] = b2[c];
    }
}

__global__ __launch_bounds__(THREADS)
void afmade_kernel(const float* __restrict__ x, float* __restrict__ out)
{
    __shared__ __align__(16) float sW0[2][256];
    __shared__ __align__(16) float sW1[2][9][256];
    __shared__ __align__(16) float sW2[2][9][32];
    __shared__ float sH0[NWARP][RPW][2][12];
    __shared__ float sH1[NWARP][RPW][2][12];

    const int tid = threadIdx.x;
    const int w   = tid >> 5;
    const int l   = tid & 31;
    const int base_row = (blockIdx.x * NWARP + w) * RPW;

    // lane l owns hidden cols {4l..4l+3, 128+4l..128+4l+3} and output col l
    float a0[2][RPW][8], a1[2][RPW][8];
    float aout[2][RPW], lssum[RPW], xreg[RPW];

#pragma unroll
    for (int net = 0; net < 2; net++) {
#pragma unroll
        for (int e = 0; e < 8; e++) {
            int c = (e < 4) ? (4 * l + e) : (128 + 4 * l + (e - 4));
            float b0v = g_b0p[net][c];
            float b1v = g_b1p[net][c];
#pragma unroll
            for (int r = 0; r < RPW; r++) { a0[net][r][e] = b0v; a1[net][r][e] = b1v; }
        }
        float b2v = g_b2[net][l];
#pragma unroll
        for (int r = 0; r < RPW; r++) aout[net][r] = b2v;
    }
#pragma unroll
    for (int r = 0; r < RPW; r++) {
        lssum[r] = 0.f;
        xreg[r]  = x[(base_row + r) * 32 + l];   // lane l holds x[., l]
    }

    for (int t = 1; t <= 32; ++t) {
        const int j = t - 1;
        // ---- emit coordinate j (aout complete through h1 deg <= t-1) ----
        float yv[RPW];
#pragma unroll
        for (int r = 0; r < RPW; r++) {
            float ls = 0.5f * aout[1][r];
            float yc = (xreg[r] - aout[0][r]) / (expf(ls) + EPSf);
            if (l == j) {
                lssum[r] += ls;
                out[(base_row + r) * 32 + j] = yc;
            }
            yv[r] = __shfl_sync(0xffffffffu, yc, j);  // lane j has the real one
        }
        if (t == 32) break;

        const int off = (t <= 9) ? 9 * (t - 1) : (72 + 8 * (t - 9));
        const int cnt = (t <= 8) ? 9 : 8;

        __syncthreads();
        // ---- stage this step's weight slices into shared (float4) ----
        if (tid < 64) {
            ((float4*)sW0)[tid]      = ((const float4*)&g_W0p[0][j][0])[tid];
            ((float4*)sW0)[64 + tid] = ((const float4*)&g_W0p[1][j][0])[tid];
        }
        {
            const int tot1 = 2 * cnt * 64;
            for (int i = tid; i < tot1; i += THREADS) {
                int net = (i < cnt * 64) ? 0 : 1;
                int rem = i - net * cnt * 64;
                int u = rem >> 6, q = rem & 63;
                ((float4*)&sW1[net][u][0])[q] =
                    ((const float4*)&g_W1p[net][off + u][0])[q];
            }
            const int tot2 = 2 * cnt * 8;
            for (int i = tid; i < tot2; i += THREADS) {
                int net = (i < cnt * 8) ? 0 : 1;
                int rem = i - net * cnt * 8;
                int u = rem >> 3, q = rem & 7;
                ((float4*)&sW2[net][u][0])[q] =
                    ((const float4*)&g_W2p[net][off + u][0])[q];
            }
        }
        __syncthreads();

        // ---- layer 0: a0 += y_j * W0p[j], then finalize h0 deg-t group ----
#pragma unroll
        for (int net = 0; net < 2; net++) {
            float4 wa = ((const float4*)&sW0[net][0])[l];
            float4 wb = ((const float4*)&sW0[net][0])[32 + l];
            float wv0[8] = {wa.x, wa.y, wa.z, wa.w, wb.x, wb.y, wb.z, wb.w};
#pragma unroll
            for (int e = 0; e < 8; e++) {
                int c = (e < 4) ? (4 * l + e) : (128 + 4 * l + (e - 4));
#pragma unroll
                for (int r = 0; r < RPW; r++)
                    a0[net][r][e] = fmaf(yv[r], wv0[e], a0[net][r][e]);
                int u = c - off;
                if ((unsigned)u < (unsigned)cnt) {
#pragma unroll
                    for (int r = 0; r < RPW; r++)
                        sH0[w][r][net][u] = fmaxf(a0[net][r][e], 0.f);
                }
            }
        }
        __syncwarp();

        // ---- layer 1: a1 += h0_group @ W1p rows, finalize h1 deg-t group ----
        for (int u = 0; u < cnt; ++u) {
#pragma unroll
            for (int net = 0; net < 2; net++) {
                float4 wa = ((const float4*)&sW1[net][u][0])[l];
                float4 wb = ((const float4*)&sW1[net][u][0])[32 + l];
                float wv1[8] = {wa.x, wa.y, wa.z, wa.w, wb.x, wb.y, wb.z, wb.w};
#pragma unroll
                for (int r = 0; r < RPW; r++) {
                    float h = sH0[w][r][net][u];
#pragma unroll
                    for (int e = 0; e < 8; e++)
                        a1[net][r][e] = fmaf(h, wv1[e], a1[net][r][e]);
                }
            }
        }
#pragma unroll
        for (int net = 0; net < 2; net++) {
#pragma unroll
            for (int e = 0; e < 8; e++) {
                int c = (e < 4) ? (4 * l + e) : (128 + 4 * l + (e - 4));
                int u = c - off;
                if ((unsigned)u < (unsigned)cnt) {
#pragma unroll
                    for (int r = 0; r < RPW; r++)
                        sH1[w][r][net][u] = fmaxf(a1[net][r][e], 0.f);
                }
            }
        }
        __syncwarp();

        // ---- output layer: aout += h1_group @ W2p rows ----
        for (int u = 0; u < cnt; ++u) {
#pragma unroll
            for (int net = 0; net < 2; net++) {
                float wv2 = sW2[net][u][l];
#pragma unroll
                for (int r = 0; r < RPW; r++)
                    aout[net][r] = fmaf(sH1[w][r][net][u], wv2, aout[net][r]);
            }
        }
    }

    // ---- logstd row-sums ----
#pragma unroll
    for (int r = 0; r < RPW; r++) {
        float s = lssum[r];
#pragma unroll
        for (int o = 16; o > 0; o >>= 1) s += __shfl_xor_sync(0xffffffffu, s, o);
        if (l == 0) out[Bb * Dd + base_row + r] = s;
    }
}

extern "C" void kernel_launch(void* const* d_in, const int* in_sizes, int n_in,
                              void* d_out, int out_size)
{
    (void)in_sizes; (void)n_in; (void)out_size;
    const float* x = (const float*)d_in[0];

    prep_kernel<<<512, 256>>>(
        (const float*)d_in[1],  (const float*)d_in[2],  (const float*)d_in[3],
        (const float*)d_in[4],  (const float*)d_in[5],  (const float*)d_in[6],
        (const float*)d_in[7],  (const float*)d_in[8],  (const float*)d_in[9],
        (const float*)d_in[10], (const float*)d_in[11], (const float*)d_in[12]);

    afmade_kernel<<<Bb / (NWARP * RPW), THREADS>>>(x, (float*)d_out);
}

// round 2
// speedup vs baseline: 1.4386x; 1.4386x over previous
#include <cuda_runtime.h>
#include <math.h>

// AFMADEBlock: incremental triangular evaluation of the MADE autoregressive
// inverse. Coordinate j of the fixed point depends only on coords < j (masked
// weights are exact 0.0f), so the reference's 32 full network passes collapse
// into ONE pass that finalizes one degree-group per step.
//
// R2: no block-level staging / __syncthreads. Warps are autonomous; weights
// are read straight from L1/L2 via __ldg with the step body fully unrolled
// (CNT templated) so loads batch with high MLP.

#define Dd 32
#define Hh 256
#define Bb 4096
#define EPSf 1e-12f
#define RPW 2                 // rows per warp
#define NWARP 4               // warps per block
#define THREADS (NWARP * 32)

// Permuted+masked weights (hidden units sorted by degree). ~656KB, static.
__device__ __align__(16) float g_W0p[2][32][256];
__device__ __align__(16) float g_W1p[2][256][256];
__device__ __align__(16) float g_W2p[2][256][32];
__device__ __align__(16) float g_b0p[2][256];
__device__ __align__(16) float g_b1p[2][256];
__device__ __align__(16) float g_b2[2][32];

// deg(i) = (i % 31) + 1 for original hidden index i.
// Sorted order: degrees 1..8 have 9 units, degrees 9..31 have 8 units.
__device__ __forceinline__ int degS(int k) {
    return (k < 72) ? (k / 9 + 1) : ((k - 72) / 8 + 9);
}
__device__ __forceinline__ int permS(int k) {
    int d, jj;
    if (k < 72) { d = k / 9 + 1;        jj = k % 9; }
    else        { d = (k - 72) / 8 + 9; jj = (k - 72) % 8; }
    return (d - 1) + 31 * jj;   // original index of k-th sorted unit
}

__global__ void prep_kernel(
    const float* __restrict__ mu_W0, const float* __restrict__ mu_b0,
    const float* __restrict__ mu_W1, const float* __restrict__ mu_b1,
    const float* __restrict__ mu_W2, const float* __restrict__ mu_b2,
    const float* __restrict__ lv_W0, const float* __restrict__ lv_b0,
    const float* __restrict__ lv_W1, const float* __restrict__ lv_b1,
    const float* __restrict__ lv_W2, const float* __restrict__ lv_b2)
{
    int idx = blockIdx.x * blockDim.x + threadIdx.x;
    if (idx >= 2 * 256 * 256) return;
    int net = idx >> 16;
    int k   = (idx >> 8) & 255;   // sorted hidden row
    int c   = idx & 255;          // sorted hidden col

    const float* W0 = net ? lv_W0 : mu_W0;
    const float* b0 = net ? lv_b0 : mu_b0;
    const float* W1 = net ? lv_W1 : mu_W1;
    const float* b1 = net ? lv_b1 : mu_b1;
    const float* W2 = net ? lv_W2 : mu_W2;
    const float* b2 = net ? lv_b2 : mu_b2;

    int dk = degS(k), pk = permS(k);
    int dc = degS(c), pc = permS(c);

    // hidden->hidden: unit c receives from unit k iff deg(c) >= deg(k)
    g_W1p[net][k][c] = (dc >= dk) ? W1[pk * 256 + pc] : 0.f;
    // input->hidden: input row k (deg k+1) feeds unit c iff deg(c) >= k+1
    if (k < 32) g_W0p[net][k][c] = (dc >= (k + 1)) ? W0[k * 256 + pc] : 0.f;
    // hidden->output: output c (deg c+1) receives unit k iff c+1 > deg(k)
    if (c < 32) g_W2p[net][k][c] = ((c + 1) > dk) ? W2[pk * 32 + c] : 0.f;
    if (k == 0) {
        g_b0p[net][c] = b0[pc];
        g_b1p[net][c] = b1[pc];
        if (c < 32) g_b2[net][c] = b2[c];
    }
}

// One degree-group step: push y_j through layer0, finalize h0 group (CNT
// units), push through layer1, finalize h1 group, push through layer2.
template<int CNT>
__device__ __forceinline__ void do_step(
    int l, int off, int j, const float yv[RPW],
    float a0[2][RPW][8], float a1[2][RPW][8], float aout[2][RPW],
    float (*sH0)[RPW][12], float (*sH1)[RPW][12])
{
    // ---- layer 0: a0 += y_j * W0p[j], finalize h0 deg-t group ----
#pragma unroll
    for (int net = 0; net < 2; net++) {
        const float4* w0r = (const float4*)&g_W0p[net][j][0];
        float4 wa = __ldg(w0r + l);
        float4 wb = __ldg(w0r + 32 + l);
        float wv0[8] = {wa.x, wa.y, wa.z, wa.w, wb.x, wb.y, wb.z, wb.w};
#pragma unroll
        for (int e = 0; e < 8; e++) {
            int c = (e < 4) ? (4 * l + e) : (128 + 4 * l + (e - 4));
#pragma unroll
            for (int r = 0; r < RPW; r++)
                a0[net][r][e] = fmaf(yv[r], wv0[e], a0[net][r][e]);
            int u = c - off;
            if ((unsigned)u < (unsigned)CNT) {
#pragma unroll
                for (int r = 0; r < RPW; r++)
                    sH0[net][r][u] = fmaxf(a0[net][r][e], 0.f);
            }
        }
    }
    __syncwarp();

    // ---- layer 1: a1 += h0_group @ W1p rows ----
#pragma unroll
    for (int u = 0; u < CNT; u++) {
#pragma unroll
        for (int net = 0; net < 2; net++) {
            const float4* w1r = (const float4*)&g_W1p[net][off + u][0];
            float4 wa = __ldg(w1r + l);
            float4 wb = __ldg(w1r + 32 + l);
            float wv1[8] = {wa.x, wa.y, wa.z, wa.w, wb.x, wb.y, wb.z, wb.w};
#pragma unroll
            for (int r = 0; r < RPW; r++) {
                float h = sH0[net][r][u];
#pragma unroll
                for (int e = 0; e < 8; e++)
                    a1[net][r][e] = fmaf(h, wv1[e], a1[net][r][e]);
            }
        }
    }
    // finalize h1 deg-t group
#pragma unroll
    for (int net = 0; net < 2; net++) {
#pragma unroll
        for (int e = 0; e < 8; e++) {
            int c = (e < 4) ? (4 * l + e) : (128 + 4 * l + (e - 4));
            int u = c - off;
            if ((unsigned)u < (unsigned)CNT) {
#pragma unroll
                for (int r = 0; r < RPW; r++)
                    sH1[net][r][u] = fmaxf(a1[net][r][e], 0.f);
            }
        }
    }
    __syncwarp();

    // ---- output layer: aout += h1_group @ W2p rows ----
#pragma unroll
    for (int u = 0; u < CNT; u++) {
#pragma unroll
        for (int net = 0; net < 2; net++) {
            float wv2 = __ldg(&g_W2p[net][off + u][l]);
#pragma unroll
            for (int r = 0; r < RPW; r++)
                aout[net][r] = fmaf(sH1[net][r][u], wv2, aout[net][r]);
        }
    }
}

__global__ __launch_bounds__(THREADS, 4)
void afmade_kernel(const float* __restrict__ x, float* __restrict__ out)
{
    __shared__ float sH0[NWARP][2][RPW][12];
    __shared__ float sH1[NWARP][2][RPW][12];

    const int tid = threadIdx.x;
    const int w   = tid >> 5;
    const int l   = tid & 31;
    const int base_row = (blockIdx.x * NWARP + w) * RPW;

    // lane l owns hidden cols {4l..4l+3, 128+4l..128+4l+3} and output col l
    float a0[2][RPW][8], a1[2][RPW][8];
    float aout[2][RPW], lssum[RPW], xreg[RPW];

#pragma unroll
    for (int net = 0; net < 2; net++) {
#pragma unroll
        for (int e = 0; e < 8; e++) {
            int c = (e < 4) ? (4 * l + e) : (128 + 4 * l + (e - 4));
            float b0v = g_b0p[net][c];
            float b1v = g_b1p[net][c];
#pragma unroll
            for (int r = 0; r < RPW; r++) { a0[net][r][e] = b0v; a1[net][r][e] = b1v; }
        }
        float b2v = g_b2[net][l];
#pragma unroll
        for (int r = 0; r < RPW; r++) aout[net][r] = b2v;
    }
#pragma unroll
    for (int r = 0; r < RPW; r++) {
        lssum[r] = 0.f;
        xreg[r]  = x[(base_row + r) * 32 + l];   // lane l holds x[., l]
    }

    for (int t = 1; t <= 32; ++t) {
        const int j = t - 1;
        // ---- emit coordinate j ----
        float yv[RPW];
#pragma unroll
        for (int r = 0; r < RPW; r++) {
            float ls = 0.5f * aout[1][r];
            float yc = __fdividef(xreg[r] - aout[0][r], __expf(ls) + EPSf);
            if (l == j) {
                lssum[r] += ls;
                out[(base_row + r) * 32 + j] = yc;
            }
            yv[r] = __shfl_sync(0xffffffffu, yc, j);  // lane j has the real one
        }
        if (t == 32) break;

        const int off = (t <= 9) ? 9 * (t - 1) : (72 + 8 * (t - 9));
        if (t <= 8)
            do_step<9>(l, off, j, yv, a0, a1, aout, sH0[w], sH1[w]);
        else
            do_step<8>(l, off, j, yv, a0, a1, aout, sH0[w], sH1[w]);
    }

    // ---- logstd row-sums ----
#pragma unroll
    for (int r = 0; r < RPW; r++) {
        float s = lssum[r];
#pragma unroll
        for (int o = 16; o > 0; o >>= 1) s += __shfl_xor_sync(0xffffffffu, s, o);
        if (l == 0) out[Bb * Dd + base_row + r] = s;
    }
}

extern "C" void kernel_launch(void* const* d_in, const int* in_sizes, int n_in,
                              void* d_out, int out_size)
{
    (void)in_sizes; (void)n_in; (void)out_size;
    const float* x = (const float*)d_in[0];

    prep_kernel<<<512, 256>>>(
        (const float*)d_in[1],  (const float*)d_in[2],  (const float*)d_in[3],
        (const float*)d_in[4],  (const float*)d_in[5],  (const float*)d_in[6],
        (const float*)d_in[7],  (const float*)d_in[8],  (const float*)d_in[9],
        (const float*)d_in[10], (const float*)d_in[11], (const float*)d_in[12]);

    afmade_kernel<<<Bb / (NWARP * RPW), THREADS>>>(x, (float*)d_out);
}

// round 4
// speedup vs baseline: 1.5327x; 1.0654x over previous
#include <cuda_runtime.h>
#include <cstdint>
#include <math.h>

// AFMADEBlock: incremental triangular evaluation of the MADE autoregressive
// inverse. One degree-group finalized per step (31 steps) instead of the
// reference's 32 full network passes.
//
// R4 (= R3 + include fix): per-step weights (<=22KB) double-buffered in
// shared memory via a cp.async pipeline (prefetch step t+1 while computing
// step t). Consumers read weights from smem (LDS, hideable) instead of L2
// (~240cyc, which was the R2 bottleneck: issue=24%, fma=13.6%).

#define Dd 32
#define Hh 256
#define Bb 4096
#define EPSf 1e-12f
#define RPW 2                 // rows per warp
#define NWARP 4               // warps per block
#define THREADS (NWARP * 32)

// Permuted+masked weights (hidden units sorted by degree). ~656KB, static.
__device__ __align__(16) float g_W0p[2][32][256];
__device__ __align__(16) float g_W1p[2][256][256];
__device__ __align__(16) float g_W2p[2][256][32];
__device__ __align__(16) float g_b0p[2][256];
__device__ __align__(16) float g_b1p[2][256];
__device__ __align__(16) float g_b2[2][32];

// deg(i) = (i % 31) + 1 for original hidden index i.
// Sorted order: degrees 1..8 have 9 units, degrees 9..31 have 8 units.
__device__ __forceinline__ int degS(int k) {
    return (k < 72) ? (k / 9 + 1) : ((k - 72) / 8 + 9);
}
__device__ __forceinline__ int permS(int k) {
    int d, jj;
    if (k < 72) { d = k / 9 + 1;        jj = k % 9; }
    else        { d = (k - 72) / 8 + 9; jj = (k - 72) % 8; }
    return (d - 1) + 31 * jj;   // original index of k-th sorted unit
}

__global__ void prep_kernel(
    const float* __restrict__ mu_W0, const float* __restrict__ mu_b0,
    const float* __restrict__ mu_W1, const float* __restrict__ mu_b1,
    const float* __restrict__ mu_W2, const float* __restrict__ mu_b2,
    const float* __restrict__ lv_W0, const float* __restrict__ lv_b0,
    const float* __restrict__ lv_W1, const float* __restrict__ lv_b1,
    const float* __restrict__ lv_W2, const float* __restrict__ lv_b2)
{
    int idx = blockIdx.x * blockDim.x + threadIdx.x;
    if (idx >= 2 * 256 * 256) return;
    int net = idx >> 16;
    int k   = (idx >> 8) & 255;   // sorted hidden row
    int c   = idx & 255;          // sorted hidden col

    const float* W0 = net ? lv_W0 : mu_W0;
    const float* b0 = net ? lv_b0 : mu_b0;
    const float* W1 = net ? lv_W1 : mu_W1;
    const float* b1 = net ? lv_b1 : mu_b1;
    const float* W2 = net ? lv_W2 : mu_W2;
    const float* b2 = net ? lv_b2 : mu_b2;

    int dk = degS(k), pk = permS(k);
    int dc = degS(c), pc = permS(c);

    g_W1p[net][k][c] = (dc >= dk) ? W1[pk * 256 + pc] : 0.f;
    if (k < 32) g_W0p[net][k][c] = (dc >= (k + 1)) ? W0[k * 256 + pc] : 0.f;
    if (c < 32) g_W2p[net][k][c] = ((c + 1) > dk) ? W2[pk * 32 + c] : 0.f;
    if (k == 0) {
        g_b0p[net][c] = b0[pc];
        g_b1p[net][c] = b1[pc];
        if (c < 32) g_b2[net][c] = b2[c];
    }
}

__device__ __forceinline__ void cp16(void* s, const void* g) {
    unsigned int sa = (unsigned int)__cvta_generic_to_shared(s);
    asm volatile("cp.async.cg.shared.global [%0], [%1], 16;" :: "r"(sa), "l"(g));
}
__device__ __forceinline__ void cp_commit() {
    asm volatile("cp.async.commit_group;");
}
__device__ __forceinline__ void cp_wait_all() {
    asm volatile("cp.async.wait_group 0;");
}

// One degree-group step using smem-resident weights.
template<int CNT>
__device__ __forceinline__ void do_step(
    int l, int off, const float yv[RPW],
    float a0[2][RPW][8], float a1[2][RPW][8], float aout[2][RPW],
    const float4 (*sW0)[64], const float4 (*sW1)[9][64], const float4 (*sW2)[9][8],
    float (*sH0)[RPW][9], float (*sH1)[RPW][9])
{
    // ---- layer 0: a0 += y_j * W0p[j], finalize h0 deg-t group ----
#pragma unroll
    for (int net = 0; net < 2; net++) {
        float4 wa = sW0[net][l];
        float4 wb = sW0[net][32 + l];
        float wv0[8] = {wa.x, wa.y, wa.z, wa.w, wb.x, wb.y, wb.z, wb.w};
#pragma unroll
        for (int e = 0; e < 8; e++) {
            int c = (e < 4) ? (4 * l + e) : (128 + 4 * l + (e - 4));
#pragma unroll
            for (int r = 0; r < RPW; r++)
                a0[net][r][e] = fmaf(yv[r], wv0[e], a0[net][r][e]);
            int u = c - off;
            if ((unsigned)u < (unsigned)CNT) {
#pragma unroll
                for (int r = 0; r < RPW; r++)
                    sH0[net][r][u] = fmaxf(a0[net][r][e], 0.f);
            }
        }
    }
    __syncwarp();

    // ---- layer 1: a1 += h0_group @ W1p rows ----
#pragma unroll
    for (int u = 0; u < CNT; u++) {
#pragma unroll
        for (int net = 0; net < 2; net++) {
            float4 wa = sW1[net][u][l];
            float4 wb = sW1[net][u][32 + l];
            float wv1[8] = {wa.x, wa.y, wa.z, wa.w, wb.x, wb.y, wb.z, wb.w};
#pragma unroll
            for (int r = 0; r < RPW; r++) {
                float h = sH0[net][r][u];
#pragma unroll
                for (int e = 0; e < 8; e++)
                    a1[net][r][e] = fmaf(h, wv1[e], a1[net][r][e]);
            }
        }
    }
    // finalize h1 deg-t group
#pragma unroll
    for (int net = 0; net < 2; net++) {
#pragma unroll
        for (int e = 0; e < 8; e++) {
            int c = (e < 4) ? (4 * l + e) : (128 + 4 * l + (e - 4));
            int u = c - off;
            if ((unsigned)u < (unsigned)CNT) {
#pragma unroll
                for (int r = 0; r < RPW; r++)
                    sH1[net][r][u] = fmaxf(a1[net][r][e], 0.f);
            }
        }
    }
    __syncwarp();

    // ---- output layer: aout += h1_group @ W2p rows ----
#pragma unroll
    for (int u = 0; u < CNT; u++) {
#pragma unroll
        for (int net = 0; net < 2; net++) {
            float wv2 = ((const float*)&sW2[net][u][0])[l];
#pragma unroll
            for (int r = 0; r < RPW; r++)
                aout[net][r] = fmaf(sH1[net][r][u], wv2, aout[net][r]);
        }
    }
}

// Prefetch the weights for step t (1-based) into the given buffer.
__device__ __forceinline__ void prefetch_step(
    int t, int tid,
    float4 (*sW0)[64], float4 (*sW1)[9][64], float4 (*sW2)[9][8])
{
    const int j   = t - 1;
    const int off = (t <= 9) ? 9 * (t - 1) : (72 + 8 * (t - 9));
    const int cnt = (t <= 8) ? 9 : 8;

    // W0 row j: 2 nets x 64 float4
    if (tid < 128) {
        int net = tid >> 6, q = tid & 63;
        cp16(&sW0[net][q], &g_W0p[net][j][q * 4]);
    }
    // W1 rows off..off+cnt-1: 2 nets x cnt x 64 float4
#pragma unroll
    for (int net = 0; net < 2; net++)
        for (int i = tid; i < cnt * 64; i += THREADS) {
            int u = i >> 6, q = i & 63;
            cp16(&sW1[net][u][q], &g_W1p[net][off + u][q * 4]);
        }
    // W2 rows: 2 nets x cnt x 8 float4
#pragma unroll
    for (int net = 0; net < 2; net++)
        for (int i = tid; i < cnt * 8; i += THREADS) {
            int u = i >> 3, q = i & 7;
            cp16(&sW2[net][u][q], &g_W2p[net][off + u][q * 4]);
        }
}

__global__ __launch_bounds__(THREADS, 4)
void afmade_kernel(const float* __restrict__ x, float* __restrict__ out)
{
    __shared__ float4 sW0[2][2][64];       //  4 KB  [buf][net][q]
    __shared__ float4 sW1[2][2][9][64];    // 36 KB  [buf][net][u][q]
    __shared__ float4 sW2[2][2][9][8];     // 4.5 KB [buf][net][u][q]
    __shared__ float  sH0[NWARP][2][RPW][9];
    __shared__ float  sH1[NWARP][2][RPW][9];

    const int tid = threadIdx.x;
    const int w   = tid >> 5;
    const int l   = tid & 31;
    const int base_row = (blockIdx.x * NWARP + w) * RPW;

    // lane l owns hidden cols {4l..4l+3, 128+4l..128+4l+3} and output col l
    float a0[2][RPW][8], a1[2][RPW][8];
    float aout[2][RPW], lssum[RPW], xreg[RPW];

#pragma unroll
    for (int net = 0; net < 2; net++) {
#pragma unroll
        for (int e = 0; e < 8; e++) {
            int c = (e < 4) ? (4 * l + e) : (128 + 4 * l + (e - 4));
            float b0v = g_b0p[net][c];
            float b1v = g_b1p[net][c];
#pragma unroll
            for (int r = 0; r < RPW; r++) { a0[net][r][e] = b0v; a1[net][r][e] = b1v; }
        }
        float b2v = g_b2[net][l];
#pragma unroll
        for (int r = 0; r < RPW; r++) aout[net][r] = b2v;
    }
#pragma unroll
    for (int r = 0; r < RPW; r++) {
        lssum[r] = 0.f;
        xreg[r]  = x[(base_row + r) * 32 + l];   // lane l holds x[., l]
    }

    // Prologue: prefetch step 1 into buffer 0.
    prefetch_step(1, tid, sW0[0], sW1[0], sW2[0]);
    cp_commit();

    int buf = 0;
    for (int t = 1; t <= 32; ++t) {
        const int j = t - 1;
        // ---- emit coordinate j (registers only; overlaps in-flight prefetch) ----
        float yv[RPW];
#pragma unroll
        for (int r = 0; r < RPW; r++) {
            float ls = 0.5f * aout[1][r];
            float yc = __fdividef(xreg[r] - aout[0][r], __expf(ls) + EPSf);
            if (l == j) {
                lssum[r] += ls;
                out[(base_row + r) * 32 + j] = yc;
            }
            yv[r] = __shfl_sync(0xffffffffu, yc, j);  // lane j has the real one
        }
        if (t == 32) break;

        // Wait for this step's weights; barrier also retires the other buffer.
        cp_wait_all();
        __syncthreads();

        // Prefetch next step into the buffer just freed (overlaps do_step).
        if (t < 31) {
            prefetch_step(t + 1, tid, sW0[buf ^ 1], sW1[buf ^ 1], sW2[buf ^ 1]);
            cp_commit();
        }

        const int off = (t <= 9) ? 9 * (t - 1) : (72 + 8 * (t - 9));
        if (t <= 8)
            do_step<9>(l, off, yv, a0, a1, aout,
                       sW0[buf], sW1[buf], sW2[buf], sH0[w], sH1[w]);
        else
            do_step<8>(l, off, yv, a0, a1, aout,
                       sW0[buf], sW1[buf], sW2[buf], sH0[w], sH1[w]);
        buf ^= 1;
    }

    // ---- logstd row-sums ----
#pragma unroll
    for (int r = 0; r < RPW; r++) {
        float s = lssum[r];
#pragma unroll
        for (int o = 16; o > 0; o >>= 1) s += __shfl_xor_sync(0xffffffffu, s, o);
        if (l == 0) out[Bb * Dd + base_row + r] = s;
    }
}

extern "C" void kernel_launch(void* const* d_in, const int* in_sizes, int n_in,
                              void* d_out, int out_size)
{
    (void)in_sizes; (void)n_in; (void)out_size;
    const float* x = (const float*)d_in[0];

    prep_kernel<<<512, 256>>>(
        (const float*)d_in[1],  (const float*)d_in[2],  (const float*)d_in[3],
        (const float*)d_in[4],  (const float*)d_in[5],  (const float*)d_in[6],
        (const float*)d_in[7],  (const float*)d_in[8],  (const float*)d_in[9],
        (const float*)d_in[10], (const float*)d_in[11], (const float*)d_in[12]);

    afmade_kernel<<<Bb / (NWARP * RPW), THREADS>>>(x, (float*)d_out);
}

// round 5
// speedup vs baseline: 2.6115x; 1.7038x over previous
#include <cuda_runtime.h>
#include <cstdint>
#include <math.h>

// AFMADEBlock: incremental triangular evaluation of the MADE autoregressive
// inverse. One degree-group finalized per step (31 steps).
//
// R5: (a) lane->column remap (64e+2l+i) so fully-dead 64-col blocks are
// skipped uniformly (4 static (CNT,E0) step variants), (b) RPW=4 so each
// weight LDS serves 4 rows (smem crossbar was the R4 bottleneck, L1=71.7%),
// (c) packed fma.rn.f32x2 halves FMA issue count, (d) cp.async double
// buffer retained, prefetching only alive columns.

#define Dd 32
#define Bb 4096
#define EPSf 1e-12f
#define RPW 4                 // rows per warp
#define NWARP 4               // warps per block
#define THREADS (NWARP * 32)
#define ROWS_PER_BLOCK (NWARP * RPW)   // 16
#define GRID (Bb / ROWS_PER_BLOCK)     // 256

// Permuted+masked weights (hidden units sorted by degree). ~656KB, static.
__device__ __align__(16) float g_W0p[2][32][256];
__device__ __align__(16) float g_W1p[2][256][256];
__device__ __align__(16) float g_W2p[2][256][32];
__device__ __align__(16) float g_b0p[2][256];
__device__ __align__(16) float g_b1p[2][256];
__device__ __align__(16) float g_b2[2][32];

// deg(i) = (i % 31) + 1 for original hidden index i.
// Sorted order: degrees 1..8 have 9 units, degrees 9..31 have 8 units.
__device__ __forceinline__ int degS(int k) {
    return (k < 72) ? (k / 9 + 1) : ((k - 72) / 8 + 9);
}
__device__ __forceinline__ int permS(int k) {
    int d, jj;
    if (k < 72) { d = k / 9 + 1;        jj = k % 9; }
    else        { d = (k - 72) / 8 + 9; jj = (k - 72) % 8; }
    return (d - 1) + 31 * jj;   // original index of k-th sorted unit
}

__global__ void prep_kernel(
    const float* __restrict__ mu_W0, const float* __restrict__ mu_b0,
    const float* __restrict__ mu_W1, const float* __restrict__ mu_b1,
    const float* __restrict__ mu_W2, const float* __restrict__ mu_b2,
    const float* __restrict__ lv_W0, const float* __restrict__ lv_b0,
    const float* __restrict__ lv_W1, const float* __restrict__ lv_b1,
    const float* __restrict__ lv_W2, const float* __restrict__ lv_b2)
{
    int idx = blockIdx.x * blockDim.x + threadIdx.x;
    if (idx >= 2 * 256 * 256) return;
    int net = idx >> 16;
    int k   = (idx >> 8) & 255;   // sorted hidden row
    int c   = idx & 255;          // sorted hidden col

    const float* W0 = net ? lv_W0 : mu_W0;
    const float* b0 = net ? lv_b0 : mu_b0;
    const float* W1 = net ? lv_W1 : mu_W1;
    const float* b1 = net ? lv_b1 : mu_b1;
    const float* W2 = net ? lv_W2 : mu_W2;
    const float* b2 = net ? lv_b2 : mu_b2;

    int dk = degS(k), pk = permS(k);
    int dc = degS(c), pc = permS(c);

    g_W1p[net][k][c] = (dc >= dk) ? W1[pk * 256 + pc] : 0.f;
    if (k < 32) g_W0p[net][k][c] = (dc >= (k + 1)) ? W0[k * 256 + pc] : 0.f;
    if (c < 32) g_W2p[net][k][c] = ((c + 1) > dk) ? W2[pk * 32 + c] : 0.f;
    if (k == 0) {
        g_b0p[net][c] = b0[pc];
        g_b1p[net][c] = b1[pc];
        if (c < 32) g_b2[net][c] = b2[c];
    }
}

__device__ __forceinline__ void cp16(void* s, const void* g) {
    unsigned int sa = (unsigned int)__cvta_generic_to_shared(s);
    asm volatile("cp.async.cg.shared.global [%0], [%1], 16;" :: "r"(sa), "l"(g));
}
__device__ __forceinline__ void cp_commit() {
    asm volatile("cp.async.commit_group;");
}
__device__ __forceinline__ void cp_wait_all() {
    asm volatile("cp.async.wait_group 0;");
}

// Packed dual-fp32 FMA: d = a*b + d (elementwise on the two f32 halves).
__device__ __forceinline__ void ffma2(float2& d, const float2& a, const float2& b) {
    asm("fma.rn.f32x2 %0, %1, %2, %0;"
        : "+l"(reinterpret_cast<unsigned long long&>(d))
        : "l"(reinterpret_cast<const unsigned long long&>(a)),
          "l"(reinterpret_cast<const unsigned long long&>(b)));
}

// One degree-group step. Lane l owns cols 64e+2l+{0,1}, e in [E0,4).
// CNT = group size, E0 = first alive 64-col block (= off>>6).
template<int CNT, int E0>
__device__ __forceinline__ void do_step(
    int l, int off, int buf, const float2 y2[RPW],
    float2 a0[2][RPW][4], float2 a1[2][RPW][4], float2 aout2[2][2],
    const float* SW0, const float* SW1, const float* SW2,
    float2 (*sH0)[9][RPW], float2 (*sH1)[9][2])
{
    // ---- layer 0: a0 += y_j * W0row ----
#pragma unroll
    for (int net = 0; net < 2; net++) {
#pragma unroll
        for (int e = E0; e < 4; e++) {
            float2 wv = *(const float2*)(SW0 + (buf * 2 + net) * 256 + 64 * e + 2 * l);
#pragma unroll
            for (int r = 0; r < RPW; r++) ffma2(a0[net][r][e], wv, y2[r]);
        }
    }
    // finalize h0 group [off, off+CNT) -> sH0[net][u][r] = {h,h}
#pragma unroll
    for (int net = 0; net < 2; net++) {
#pragma unroll
        for (int e = E0; e < 4; e++) {
            int u0 = 64 * e + 2 * l - off;
            if (u0 >= 0 && u0 < CNT) {
#pragma unroll
                for (int r = 0; r < RPW; r++) {
                    float h = fmaxf(a0[net][r][e].x, 0.f);
                    sH0[net][u0][r] = make_float2(h, h);
                }
            }
            if (u0 + 1 >= 0 && u0 + 1 < CNT) {
#pragma unroll
                for (int r = 0; r < RPW; r++) {
                    float h = fmaxf(a0[net][r][e].y, 0.f);
                    sH0[net][u0 + 1][r] = make_float2(h, h);
                }
            }
        }
    }
    __syncwarp();

    // ---- layer 1: a1 += h0_group @ W1 rows ----
#pragma unroll
    for (int net = 0; net < 2; net++) {
#pragma unroll
        for (int u = 0; u < CNT; u++) {
            const float* wr = SW1 + ((buf * 2 + net) * 9 + u) * 256;
            float2 wv[4];
#pragma unroll
            for (int e = E0; e < 4; e++)
                wv[e] = *(const float2*)(wr + 64 * e + 2 * l);
#pragma unroll
            for (int r = 0; r < RPW; r++) {
                float2 h2 = sH0[net][u][r];        // {h,h} broadcast
#pragma unroll
                for (int e = E0; e < 4; e++) ffma2(a1[net][r][e], wv[e], h2);
            }
        }
    }
    // finalize h1 group -> sH1[net][u][rp] = {h(2rp), h(2rp+1)}
#pragma unroll
    for (int net = 0; net < 2; net++) {
#pragma unroll
        for (int e = E0; e < 4; e++) {
            int u0 = 64 * e + 2 * l - off;
            if (u0 >= 0 && u0 < CNT) {
#pragma unroll
                for (int rp = 0; rp < 2; rp++)
                    sH1[net][u0][rp] = make_float2(
                        fmaxf(a1[net][2 * rp][e].x, 0.f),
                        fmaxf(a1[net][2 * rp + 1][e].x, 0.f));
            }
            if (u0 + 1 >= 0 && u0 + 1 < CNT) {
#pragma unroll
                for (int rp = 0; rp < 2; rp++)
                    sH1[net][u0 + 1][rp] = make_float2(
                        fmaxf(a1[net][2 * rp][e].y, 0.f),
                        fmaxf(a1[net][2 * rp + 1][e].y, 0.f));
            }
        }
    }
    __syncwarp();

    // ---- layer 2: aout += h1_group @ W2 rows (pairs over rows) ----
#pragma unroll
    for (int net = 0; net < 2; net++) {
#pragma unroll
        for (int u = 0; u < CNT; u++) {
            float wvf = SW2[((buf * 2 + net) * 9 + u) * 32 + l];
            float2 w2 = make_float2(wvf, wvf);
#pragma unroll
            for (int rp = 0; rp < 2; rp++) {
                float2 h2 = sH1[net][u][rp];
                ffma2(aout2[net][rp], h2, w2);
            }
        }
    }
}

// Prefetch weights for a step (row j, group offset off) into buffer buf.
// Only alive columns [64*E0, 256) are fetched.
template<int CNT, int E0>
__device__ __forceinline__ void prefetch_step(
    int j, int off, int tid, int buf,
    float* SW0, float* SW1, float* SW2)
{
    constexpr int KC = 64 - 16 * E0;   // 16B chunks per W0/W1 row
#pragma unroll
    for (int net = 0; net < 2; net++) {
        if (tid < KC)
            cp16(SW0 + (buf * 2 + net) * 256 + 64 * E0 + 4 * tid,
                 &g_W0p[net][j][64 * E0 + 4 * tid]);
        for (int i = tid; i < CNT * KC; i += THREADS) {
            int u = i / KC, q = i % KC;
            cp16(SW1 + ((buf * 2 + net) * 9 + u) * 256 + 64 * E0 + 4 * q,
                 &g_W1p[net][off + u][64 * E0 + 4 * q]);
        }
        for (int i = tid; i < CNT * 8; i += THREADS) {
            int u = i >> 3, q = i & 7;
            cp16(SW2 + ((buf * 2 + net) * 9 + u) * 32 + 4 * q,
                 &g_W2p[net][off + u][4 * q]);
        }
    }
}

__global__ __launch_bounds__(THREADS, 2)
void afmade_kernel(const float* __restrict__ x, float* __restrict__ out)
{
    // dynamic smem: SW0 [2buf][2net][256] | SW1 [2][2][9][256] | SW2 [2][2][9][32]
    extern __shared__ __align__(16) unsigned char dynsm[];
    float* SW0 = (float*)dynsm;          // 1024 floats
    float* SW1 = SW0 + 1024;             // 9216 floats
    float* SW2 = SW1 + 9216;             // 1152 floats

    __shared__ float2 sH0s[NWARP][2][9][RPW];
    __shared__ float2 sH1s[NWARP][2][9][2];

    const int tid = threadIdx.x;
    const int w   = tid >> 5;
    const int l   = tid & 31;
    const int base_row = blockIdx.x * ROWS_PER_BLOCK + w * RPW;

    float2 a0[2][RPW][4], a1[2][RPW][4], aout2[2][2];
    float  lssum[RPW], xr[RPW];

#pragma unroll
    for (int net = 0; net < 2; net++) {
#pragma unroll
        for (int e = 0; e < 4; e++) {
            float2 b0v = *(const float2*)&g_b0p[net][64 * e + 2 * l];
            float2 b1v = *(const float2*)&g_b1p[net][64 * e + 2 * l];
#pragma unroll
            for (int r = 0; r < RPW; r++) { a0[net][r][e] = b0v; a1[net][r][e] = b1v; }
        }
        float b2v = g_b2[net][l];
        aout2[net][0] = make_float2(b2v, b2v);
        aout2[net][1] = make_float2(b2v, b2v);
    }
#pragma unroll
    for (int r = 0; r < RPW; r++) {
        lssum[r] = 0.f;
        xr[r]    = x[(base_row + r) * 32 + l];   // lane l holds x[., l]
    }

    // Prologue: prefetch step 1 into buffer 0.
    prefetch_step<9, 0>(0, 0, tid, 0, SW0, SW1, SW2);
    cp_commit();

    int buf = 0;
    for (int t = 1; t <= 32; ++t) {
        const int j = t - 1;
        // ---- emit coordinate j (registers only; overlaps in-flight prefetch) ----
        float2 y2[RPW];
#pragma unroll
        for (int r = 0; r < RPW; r++) {
            float mu = (r & 1) ? aout2[0][r >> 1].y : aout2[0][r >> 1].x;
            float lv = (r & 1) ? aout2[1][r >> 1].y : aout2[1][r >> 1].x;
            float ls = 0.5f * lv;
            float yc = __fdividef(xr[r] - mu, __expf(ls) + EPSf);
            if (l == j) {
                lssum[r] += ls;
                out[(base_row + r) * 32 + j] = yc;
            }
            float yv = __shfl_sync(0xffffffffu, yc, j);
            y2[r] = make_float2(yv, yv);
        }
        if (t == 32) break;

        cp_wait_all();
        __syncthreads();

        if (t < 31) {
            const int tn = t + 1, jn = tn - 1;
            const int offn = (tn <= 9) ? 9 * (tn - 1) : 72 + 8 * (tn - 9);
            if (tn <= 8)       prefetch_step<9, 0>(jn, offn, tid, buf ^ 1, SW0, SW1, SW2);
            else if (tn <= 15) prefetch_step<8, 1>(jn, offn, tid, buf ^ 1, SW0, SW1, SW2);
            else if (tn <= 23) prefetch_step<8, 2>(jn, offn, tid, buf ^ 1, SW0, SW1, SW2);
            else               prefetch_step<8, 3>(jn, offn, tid, buf ^ 1, SW0, SW1, SW2);
            cp_commit();
        }

        const int off = (t <= 9) ? 9 * (t - 1) : 72 + 8 * (t - 9);
        if (t <= 8)
            do_step<9, 0>(l, off, buf, y2, a0, a1, aout2, SW0, SW1, SW2, sH0s[w], sH1s[w]);
        else if (t <= 15)
            do_step<8, 1>(l, off, buf, y2, a0, a1, aout2, SW0, SW1, SW2, sH0s[w], sH1s[w]);
        else if (t <= 23)
            do_step<8, 2>(l, off, buf, y2, a0, a1, aout2, SW0, SW1, SW2, sH0s[w], sH1s[w]);
        else
            do_step<8, 3>(l, off, buf, y2, a0, a1, aout2, SW0, SW1, SW2, sH0s[w], sH1s[w]);
        buf ^= 1;
    }

    // ---- logstd row-sums (lane l holds coordinate l's contribution) ----
#pragma unroll
    for (int r = 0; r < RPW; r++) {
        float s = lssum[r];
#pragma unroll
        for (int o = 16; o > 0; o >>= 1) s += __shfl_xor_sync(0xffffffffu, s, o);
        if (l == 0) out[Bb * Dd + base_row + r] = s;
    }
}

extern "C" void kernel_launch(void* const* d_in, const int* in_sizes, int n_in,
                              void* d_out, int out_size)
{
    (void)in_sizes; (void)n_in; (void)out_size;
    const float* x = (const float*)d_in[0];

    prep_kernel<<<512, 256>>>(
        (const float*)d_in[1],  (const float*)d_in[2],  (const float*)d_in[3],
        (const float*)d_in[4],  (const float*)d_in[5],  (const float*)d_in[6],
        (const float*)d_in[7],  (const float*)d_in[8],  (const float*)d_in[9],
        (const float*)d_in[10], (const float*)d_in[11], (const float*)d_in[12]);

    const int dyn_smem = (1024 + 9216 + 1152) * 4;   // 45568 B
    cudaFuncSetAttribute(afmade_kernel,
                         cudaFuncAttributeMaxDynamicSharedMemorySize, dyn_smem);
    afmade_kernel<<<GRID, THREADS, dyn_smem>>>(x, (float*)d_out);
}